// round 9
// baseline (speedup 1.0000x reference)
#include <cuda_runtime.h>
#include <cuda_bf16.h>
#include <math.h>

// Problem constants
#define BB   32
#define TT   2048
#define EE   256        // K
#define HH   256
#define LBL  20

// GEMM tiling
#define KC      32      // K chunk staged in smem
#define XSTR    36      // padded stride (conflict-free, 144B = 16B-aligned rows)
#define WSTR    36
#define NT_BLK  16      // T tiles of 128 rows
#define CG_BLK  8       // 2 dirs * 4 h-groups of 64

#define STAGE_FLOATS (128 * XSTR + 192 * WSTR)   // 11520 floats per stage
#define SMEM_BYTES   (2 * STAGE_FLOATS * 4)      // 92160 B (double buffered)

// ---------------- scratch (no allocations allowed) ----------------
__device__ float g_Wpack[1536 * 256];          // tf32-rounded, blocked layout
__device__ float g_bias[1536];                 // b_ih + b_hh, same layout
__device__ float g_psum[NT_BLK * BB * 512];    // per-tile partial sums
__device__ float g_pmax[NT_BLK * BB * 512];    // per-tile partial maxes
__device__ float g_doc[BB * 1024];             // [avg(512), max(512)]
__device__ float g_d1[BB * 256];               // MLP hidden

__device__ __forceinline__ float sigmoidf_(float x) { return 1.0f / (1.0f + expf(-x)); }

__device__ __forceinline__ unsigned f2tf32(float f) {
    unsigned u;
    asm("cvt.rna.tf32.f32 %0, %1;" : "=r"(u) : "f"(f));
    return u;
}

__device__ __forceinline__ void cp_async16(float* smem_dst, const float* gmem_src) {
    unsigned s = (unsigned)__cvta_generic_to_shared(smem_dst);
    asm volatile("cp.async.cg.shared.global [%0], [%1], 16;\n" :: "r"(s), "l"(gmem_src));
}
__device__ __forceinline__ void cp_async_commit() {
    asm volatile("cp.async.commit_group;\n" ::: "memory");
}
template <int N>
__device__ __forceinline__ void cp_async_wait() {
    asm volatile("cp.async.wait_group %0;\n" :: "n"(N) : "memory");
}

__device__ __forceinline__ void mma8(float& c0, float& c1, float& c2, float& c3,
                                     unsigned a0, unsigned a1, unsigned a2, unsigned a3,
                                     unsigned b0, unsigned b1) {
    asm volatile(
        "mma.sync.aligned.m16n8k8.row.col.f32.tf32.tf32.f32 "
        "{%0,%1,%2,%3}, {%4,%5,%6,%7}, {%8,%9}, {%0,%1,%2,%3};"
        : "+f"(c0), "+f"(c1), "+f"(c2), "+f"(c3)
        : "r"(a0), "r"(a1), "r"(a2), "r"(a3), "r"(b0), "r"(b1));
}

// ---------------- pack W (skip dead 'f' gate) + fuse biases ----------------
// Layout: c = ((dir*4 + hgrp)*3 + gate)*64 + j   (gate: 0=i, 1=g, 2=o), K contiguous
__global__ void pack_w_kernel(const float* __restrict__ Wf, const float* __restrict__ bif,
                              const float* __restrict__ bhf,
                              const float* __restrict__ Wr, const float* __restrict__ bir,
                              const float* __restrict__ bhr) {
    int c = blockIdx.x;          // 0..1535
    int k = threadIdx.x;         // 0..255
    int cg = c / 192, within = c % 192;
    int gate = within / 64, j = within % 64;
    int dir = cg / 4, hgrp = cg % 4;
    int gsel = (gate == 0) ? 0 : (gate == 1 ? 2 : 3);   // torch gate order i,f,g,o
    int srow = gsel * 256 + hgrp * 64 + j;
    const float* W = dir ? Wr : Wf;
    g_Wpack[c * 256 + k] = __uint_as_float(f2tf32(W[srow * 256 + k]));
    if (k == 0) {
        const float* bi = dir ? bir : bif;
        const float* bh = dir ? bhr : bhf;
        g_bias[c] = bi[srow] + bh[srow];
    }
}

// ---------------- fused GEMM + activation + masked pooling ----------------
// block: (cg, tblk, b). Computes C[128 x 192] = X_tile @ Wsub with a cp.async
// double-buffered pipeline, then h = sigmoid(o)*tanh(sigmoid(i)*tanh(g)) and
// masked partial sum/max over the 128 rows.
// Warp layout: 2 M-warps (64 rows each, mt=4) x 4 N-warps (48 cols each, nt=6).
__global__ void __launch_bounds__(256)
gemm_fused_kernel(const float* __restrict__ X, const int* __restrict__ lengths) {
    extern __shared__ float smem[];

    const int cg = blockIdx.x, tblk = blockIdx.y, b = blockIdx.z;
    const int tid = threadIdx.x, lane = tid & 31, warp = tid >> 5;
    const int wm = warp & 1, wn = warp >> 1;       // 2 M-warps x 4 N-warps
    const int m0 = b * TT + tblk * 128;
    const float* Wp = g_Wpack + (size_t)cg * 192 * 256;

    float acc[4][6][4];
#pragma unroll
    for (int mt = 0; mt < 4; mt++)
#pragma unroll
        for (int nt = 0; nt < 6; nt++)
#pragma unroll
            for (int q = 0; q < 4; q++) acc[mt][nt][q] = 0.0f;

    // precompute staging indices
    const int si = tid >> 3, sk4 = tid & 7;   // base row/col-quad for this thread

    // ---- async stage: X tile 128x32 + W tile 192x32 into buffer `st`
    auto stage = [&](int st, int kb) {
        float* Xs = smem + st * STAGE_FLOATS;
        float* Ws = Xs + 128 * XSTR;
#pragma unroll
        for (int it = 0; it < 4; it++) {
            int i = si + it * 32;
            cp_async16(Xs + i * XSTR + sk4 * 4,
                       X + (size_t)(m0 + i) * EE + kb + sk4 * 4);
        }
#pragma unroll
        for (int it = 0; it < 6; it++) {
            int n = si + it * 32;
            cp_async16(Ws + n * WSTR + sk4 * 4,
                       Wp + (size_t)n * 256 + kb + sk4 * 4);
        }
    };

    stage(0, 0);
    cp_async_commit();

    for (int kc = 0; kc < EE / KC; kc++) {
        if (kc + 1 < EE / KC) stage((kc + 1) & 1, (kc + 1) * KC);
        cp_async_commit();
        if (kc + 1 < EE / KC) cp_async_wait<1>(); else cp_async_wait<0>();
        __syncthreads();

        const float* Xs = smem + (kc & 1) * STAGE_FLOATS;
        const float* Ws = Xs + 128 * XSTR;

#pragma unroll
        for (int k8 = 0; k8 < KC / 8; k8++) {
            const int ck = k8 * 8 + (lane & 3);
            unsigned a[4][4];
#pragma unroll
            for (int mt = 0; mt < 4; mt++) {
                int r0 = wm * 64 + mt * 16 + (lane >> 2);
                a[mt][0] = __float_as_uint(Xs[r0 * XSTR + ck]);
                a[mt][1] = __float_as_uint(Xs[(r0 + 8) * XSTR + ck]);
                a[mt][2] = __float_as_uint(Xs[r0 * XSTR + ck + 4]);
                a[mt][3] = __float_as_uint(Xs[(r0 + 8) * XSTR + ck + 4]);
            }
#pragma unroll
            for (int nt = 0; nt < 6; nt++) {
                int n = wn * 48 + nt * 8 + (lane >> 2);
                unsigned b0 = __float_as_uint(Ws[n * WSTR + ck]);
                unsigned b1 = __float_as_uint(Ws[n * WSTR + ck + 4]);
#pragma unroll
                for (int mt = 0; mt < 4; mt++)
                    mma8(acc[mt][nt][0], acc[mt][nt][1], acc[mt][nt][2], acc[mt][nt][3],
                         a[mt][0], a[mt][1], a[mt][2], a[mt][3], b0, b1);
            }
        }
        __syncthreads();
    }

    // ------------- epilogue: activation + masked pooling, 32 rows at a time -------------
    float* Se = smem;                 // [32][196]
    float* Spart = smem + 32 * 196;   // [256]
    float* Mpart = Spart + 256;       // [256]

    int len = lengths[b];
    len = min(max(len, 1), TT);
    const int t0 = tblk * 128;
    const int j = tid & 63, sub = tid >> 6;     // 64 h-cols, 4 row-groups
    const float bi = g_bias[cg * 192 + j];
    const float bg = g_bias[cg * 192 + 64 + j];
    const float bo = g_bias[cg * 192 + 128 + j];
    float psum = 0.0f, pmax = -1e30f;

    for (int q = 0; q < 4; q++) {               // 32-row chunks of the 128-row tile
        if (wm == (q >> 1)) {                   // owning M-warps dump their C rows
#pragma unroll
            for (int h = 0; h < 2; h++) {
                int mt = (q & 1) * 2 + h;
                int rr = h * 16 + (lane >> 2);
                int cb = wn * 48 + (lane & 3) * 2;
#pragma unroll
                for (int nt = 0; nt < 6; nt++) {
                    Se[rr * 196 + cb + nt * 8]           = acc[mt][nt][0];
                    Se[rr * 196 + cb + nt * 8 + 1]       = acc[mt][nt][1];
                    Se[(rr + 8) * 196 + cb + nt * 8]     = acc[mt][nt][2];
                    Se[(rr + 8) * 196 + cb + nt * 8 + 1] = acc[mt][nt][3];
                }
            }
        }
        __syncthreads();
#pragma unroll
        for (int rr = 0; rr < 8; rr++) {
            int rloc = sub * 8 + rr;
            float gi = Se[rloc * 196 + j] + bi;
            float gg = Se[rloc * 196 + 64 + j] + bg;
            float go = Se[rloc * 196 + 128 + j] + bo;
            float cc = sigmoidf_(gi) * tanhf(gg);
            float h  = sigmoidf_(go) * tanhf(cc);
            int t = t0 + q * 32 + rloc;
            if (t < len) { psum += h; pmax = fmaxf(pmax, h); }
        }
        __syncthreads();
    }

    Spart[tid] = psum;
    Mpart[tid] = pmax;
    __syncthreads();
    if (tid < 64) {
        float s = Spart[tid] + Spart[64 + tid] + Spart[128 + tid] + Spart[192 + tid];
        float m = fmaxf(fmaxf(Mpart[tid], Mpart[64 + tid]),
                        fmaxf(Mpart[128 + tid], Mpart[192 + tid]));
        int dir = cg >> 2, hgrp = cg & 3;
        int col = dir * 256 + hgrp * 64 + tid;
        g_psum[(tblk * BB + b) * 512 + col] = s;
        g_pmax[(tblk * BB + b) * 512 + col] = m;
    }
}

// ---------------- deterministic reduction over T-tiles -> doc[B,1024] ----------------
__global__ void reduce_doc_kernel(const int* __restrict__ lengths) {
    int b = blockIdx.x, col = threadIdx.x;   // 512 threads
    float s = 0.0f, m = -1e30f;
#pragma unroll
    for (int t = 0; t < NT_BLK; t++) {
        s += g_psum[(t * BB + b) * 512 + col];
        m = fmaxf(m, g_pmax[(t * BB + b) * 512 + col]);
    }
    int len = lengths[b];
    len = min(max(len, 1), TT);
    g_doc[b * 1024 + col]       = s / (float)len;
    g_doc[b * 1024 + 512 + col] = m;
}

// ---------------- MLP layer 1: relu(doc) @ W1^T + b1 -> g_d1[B,256] ----------------
// grid (B, 8): each block computes 32 outputs for one batch row.
__global__ void __launch_bounds__(256) mlp1_kernel(const float* __restrict__ W1,
                                                   const float* __restrict__ b1) {
    __shared__ float sdoc[1024];
    int b = blockIdx.x, jg = blockIdx.y;
    int tid = threadIdx.x, lane = tid & 31, warp = tid >> 5;
    for (int k = tid; k < 1024; k += 256) sdoc[k] = fmaxf(g_doc[b * 1024 + k], 0.0f);
    __syncthreads();
    // warp computes 4 outputs with independent accumulators (4 LDG streams)
    int jo0 = jg * 32 + warp * 4;
    float a0 = 0.f, a1 = 0.f, a2 = 0.f, a3 = 0.f;
#pragma unroll
    for (int kk = 0; kk < 32; kk++) {
        int k = lane + kk * 32;
        float d = sdoc[k];
        a0 += d * W1[(size_t)(jo0 + 0) * 1024 + k];
        a1 += d * W1[(size_t)(jo0 + 1) * 1024 + k];
        a2 += d * W1[(size_t)(jo0 + 2) * 1024 + k];
        a3 += d * W1[(size_t)(jo0 + 3) * 1024 + k];
    }
#pragma unroll
    for (int o = 16; o > 0; o >>= 1) {
        a0 += __shfl_down_sync(0xffffffffu, a0, o);
        a1 += __shfl_down_sync(0xffffffffu, a1, o);
        a2 += __shfl_down_sync(0xffffffffu, a2, o);
        a3 += __shfl_down_sync(0xffffffffu, a3, o);
    }
    if (lane == 0) {
        g_d1[b * 256 + jo0 + 0] = a0 + b1[jo0 + 0];
        g_d1[b * 256 + jo0 + 1] = a1 + b1[jo0 + 1];
        g_d1[b * 256 + jo0 + 2] = a2 + b1[jo0 + 2];
        g_d1[b * 256 + jo0 + 3] = a3 + b1[jo0 + 3];
    }
}

// ---------------- MLP layer 2: d1 @ W2^T + b2 -> out[B,LBL] ----------------
__global__ void mlp2_kernel(const float* __restrict__ W2, const float* __restrict__ b2,
                            float* __restrict__ out) {
    __shared__ float sd1[256];
    int b = blockIdx.x, tid = threadIdx.x, lane = tid & 31, warp = tid >> 5;
    sd1[tid] = g_d1[b * 256 + tid];
    __syncthreads();
    for (int l = warp; l < LBL; l += 8) {
        float a = 0.0f;
#pragma unroll
        for (int kk = 0; kk < 8; kk++) {
            int k = lane + kk * 32;
            a += sd1[k] * W2[l * 256 + k];
        }
#pragma unroll
        for (int o = 16; o > 0; o >>= 1) a += __shfl_down_sync(0xffffffffu, a, o);
        if (lane == 0) out[b * LBL + l] = a + b2[l];
    }
}

extern "C" void kernel_launch(void* const* d_in, const int* in_sizes, int n_in,
                              void* d_out, int out_size) {
    const float* X       = (const float*)d_in[0];
    const int*   lengths = (const int*)d_in[1];
    const float* W_ih_f  = (const float*)d_in[2];
    const float* b_ih_f  = (const float*)d_in[3];
    const float* b_hh_f  = (const float*)d_in[4];
    const float* W_ih_r  = (const float*)d_in[5];
    const float* b_ih_r  = (const float*)d_in[6];
    const float* b_hh_r  = (const float*)d_in[7];
    const float* W1      = (const float*)d_in[8];
    const float* b1      = (const float*)d_in[9];
    const float* W2      = (const float*)d_in[10];
    const float* b2      = (const float*)d_in[11];
    float* out = (float*)d_out;

    cudaFuncSetAttribute(gemm_fused_kernel,
                         cudaFuncAttributeMaxDynamicSharedMemorySize, SMEM_BYTES);

    pack_w_kernel<<<1536, 256>>>(W_ih_f, b_ih_f, b_hh_f, W_ih_r, b_ih_r, b_hh_r);
    dim3 grid(CG_BLK, NT_BLK, BB);
    gemm_fused_kernel<<<grid, 256, SMEM_BYTES>>>(X, lengths);
    reduce_doc_kernel<<<BB, 512>>>(lengths);
    dim3 mgrid(BB, 8);
    mlp1_kernel<<<mgrid, 256>>>(W1, b1);
    mlp2_kernel<<<BB, 256>>>(W2, b2, out);
}